// round 10
// baseline (speedup 1.0000x reference)
#include <cuda_runtime.h>
#include <cuda_fp16.h>
#include <math.h>
#include <stdint.h>
#include <stdlib.h>

// ---------------------------------------------------------------------------
// GAT 4-layer forward.  N=100000, E=1600000, 128 feats (4h x 32d).
// R10: aggregation processes 2 edges per warp iteration (16 lanes per edge,
// uint4 = 8 fp16 features per lane) with FFMA2 accumulators -> half the LDG
// instructions, half the exps, half the FMA issue on the hot edge loop.
// GEMM (FFMA2, BM=128), CSR, layer 4 unchanged from R9.
// ---------------------------------------------------------------------------

#define MAXN 100000
#define MAXE 1600000

__device__ uint4 g_hh[MAXN * 16];     // projected features, fp16 (256B/row)
__device__ float g_act[MAXN * 128];   // activations (updated in place)
__device__ float g_el[MAXN * 4];
__device__ float g_er[MAXN * 4];
__device__ int   g_deg[MAXN];
__device__ int   g_cur[MAXN];
__device__ int   g_off[MAXN + 1];
__device__ int   g_csrc[MAXE];
__device__ int   g_bsum[128];
__device__ int   g_boff[128];
__device__ float g_h4[MAXN * 2];
__device__ float g_res4[MAXN * 2];
__device__ float g_el4[MAXN];
__device__ float g_er4[MAXN];

// ---- f32x2 helpers --------------------------------------------------------
__device__ __forceinline__ unsigned long long f32x2_pack(float a, float b) {
    unsigned long long d;
    asm("mov.b64 %0, {%1, %2};" : "=l"(d) : "f"(a), "f"(b));
    return d;
}
__device__ __forceinline__ void f32x2_unpack(float& a, float& b,
                                             unsigned long long v) {
    asm("mov.b64 {%0, %1}, %2;" : "=f"(a), "=f"(b) : "l"(v));
}
__device__ __forceinline__ unsigned long long f32x2_fma(
    unsigned long long a, unsigned long long b, unsigned long long c) {
    unsigned long long d;
    asm("fma.rn.f32x2 %0, %1, %2, %3;" : "=l"(d) : "l"(a), "l"(b), "l"(c));
    return d;
}

// ---------------------------------------------------------------------------
// CSR build
// ---------------------------------------------------------------------------
__global__ void zero_kernel(int n) {
    int i = blockIdx.x * blockDim.x + threadIdx.x;
    if (i < n) { g_deg[i] = 0; g_cur[i] = 0; }
}

__global__ void hist_kernel(const int* __restrict__ dst, int e) {
    int i = blockIdx.x * blockDim.x + threadIdx.x;
    if (i < e) atomicAdd(&g_deg[dst[i]], 1);
}

__global__ void scan1_kernel(int n) {
    __shared__ int sm[1024];
    int t = threadIdx.x;
    int i = blockIdx.x * 1024 + t;
    int v = (i < n) ? g_deg[i] : 0;
    sm[t] = v;
    __syncthreads();
    for (int o = 1; o < 1024; o <<= 1) {
        int u = (t >= o) ? sm[t - o] : 0;
        __syncthreads();
        sm[t] += u;
        __syncthreads();
    }
    if (i < n) g_off[i] = sm[t] - v;   // exclusive within block
    if (t == 1023) g_bsum[blockIdx.x] = sm[1023];
}

__global__ void scan2_kernel(int nb, int n) {
    __shared__ int sm[128];
    int t = threadIdx.x;
    int v = (t < nb) ? g_bsum[t] : 0;
    sm[t] = v;
    __syncthreads();
    for (int o = 1; o < 128; o <<= 1) {
        int u = (t >= o) ? sm[t - o] : 0;
        __syncthreads();
        sm[t] += u;
        __syncthreads();
    }
    if (t < nb) g_boff[t] = sm[t] - v;
    if (t == 127) g_off[n] = sm[127];  // total edge count
}

__global__ void scan3_kernel(int n) {
    int i = blockIdx.x * blockDim.x + threadIdx.x;
    if (i < n) g_off[i] += g_boff[i >> 10];
}

__global__ void scatter_kernel(const int* __restrict__ src,
                               const int* __restrict__ dst, int e) {
    int i = blockIdx.x * blockDim.x + threadIdx.x;
    if (i < e) {
        int d = dst[i];
        int pos = atomicAdd(&g_cur[d], 1);
        g_csrc[g_off[d] + pos] = src[i];
    }
}

// ---------------------------------------------------------------------------
// Touch kernel (prewarm only): commit all big globals.
// ---------------------------------------------------------------------------
__global__ void touch_kernel() {
    long i = (long)blockIdx.x * blockDim.x + threadIdx.x;
    long tot = (long)MAXN * 128;
    if (i < (long)MAXN * 16) g_hh[i] = make_uint4(0, 0, 0, 0);
    if (i < tot) g_act[i] = 0.f;
    if (i < MAXE) g_csrc[i] = 0;
    if (i < MAXN) {
        g_el[i * 4] = 0.f; g_er[i * 4] = 0.f;
        g_el4[i] = 0.f; g_er4[i] = 0.f;
        g_h4[i * 2] = 0.f; g_res4[i * 2] = 0.f;
        g_deg[i] = 0; g_cur[i] = 0; g_off[i] = 0;
    }
    if (i < 128) { g_bsum[i] = 0; g_boff[i] = 0; }
}

// ---------------------------------------------------------------------------
// GEMM: g_hh[n,128](fp16) = X[n,128] @ W[128,128]; epilogue computes el/er.
// BM=128, 256 threads (16x16), per-thread 8x8 tile as f32x2 pairs (FFMA2).
// ---------------------------------------------------------------------------
__global__ __launch_bounds__(256, 2) void gemm128_kernel(
    const float* __restrict__ X_ext, const float* __restrict__ W,
    const float* __restrict__ al, const float* __restrict__ ar,
    int n, int use_act) {
    const float* X = use_act ? (const float*)g_act : X_ext;
    __shared__ float Xs[32][132];  // [k][row], padded
    __shared__ float Ws[32][132];  // [k][col], padded

    int tid = threadIdx.x;
    int tx = tid & 15;   // col group: cols tx*8 .. tx*8+7 (head = tx>>2)
    int ty = tid >> 4;   // row group: rows ty*8 .. ty*8+7
    int row0 = blockIdx.x * 128;

    unsigned long long acc2[8][4];
#pragma unroll
    for (int i = 0; i < 8; i++)
#pragma unroll
        for (int j = 0; j < 4; j++) acc2[i][j] = 0ull;

    for (int kc = 0; kc < 128; kc += 32) {
        // X tile: 128 rows x 32 k, transposed into Xs[k][row]
#pragma unroll
        for (int i = tid; i < 128 * 8; i += 256) {
            int r = i >> 3;
            int kq = i & 7;
            int row = row0 + r;
            float4 v = make_float4(0.f, 0.f, 0.f, 0.f);
            if (row < n) v = ((const float4*)X)[row * 32 + (kc >> 2) + kq];
            Xs[kq * 4 + 0][r] = v.x;
            Xs[kq * 4 + 1][r] = v.y;
            Xs[kq * 4 + 2][r] = v.z;
            Xs[kq * 4 + 3][r] = v.w;
        }
        // W tile: 32 k x 128 cols
#pragma unroll
        for (int i = tid; i < 32 * 32; i += 256) {
            int k = i >> 5;
            int cq = i & 31;
            float4 v = ((const float4*)W)[(kc + k) * 32 + cq];
            *(float4*)&Ws[k][cq * 4] = v;
        }
        __syncthreads();

#pragma unroll
        for (int kk = 0; kk < 32; kk++) {
            float4 xa = *(const float4*)&Xs[kk][ty * 8];
            float4 xb = *(const float4*)&Xs[kk][ty * 8 + 4];
            float4 wa = *(const float4*)&Ws[kk][tx * 8];
            float4 wb = *(const float4*)&Ws[kk][tx * 8 + 4];
            unsigned long long wp[4];
            wp[0] = f32x2_pack(wa.x, wa.y);
            wp[1] = f32x2_pack(wa.z, wa.w);
            wp[2] = f32x2_pack(wb.x, wb.y);
            wp[3] = f32x2_pack(wb.z, wb.w);
            float xr[8] = {xa.x, xa.y, xa.z, xa.w, xb.x, xb.y, xb.z, xb.w};
#pragma unroll
            for (int i = 0; i < 8; i++) {
                unsigned long long xd = f32x2_pack(xr[i], xr[i]);
#pragma unroll
                for (int j = 0; j < 4; j++)
                    acc2[i][j] = f32x2_fma(xd, wp[j], acc2[i][j]);
            }
        }
        __syncthreads();
    }

    // epilogue: fp16 h + fused el/er (this thread's 8 cols lie in head tx>>2)
    float4 alA = ((const float4*)al)[tx * 2];
    float4 alB = ((const float4*)al)[tx * 2 + 1];
    float4 arA = ((const float4*)ar)[tx * 2];
    float4 arB = ((const float4*)ar)[tx * 2 + 1];
#pragma unroll
    for (int i = 0; i < 8; i++) {
        int row = row0 + ty * 8 + i;
        float a0, a1, a2, a3, a4, a5, a6, a7;
        f32x2_unpack(a0, a1, acc2[i][0]);
        f32x2_unpack(a2, a3, acc2[i][1]);
        f32x2_unpack(a4, a5, acc2[i][2]);
        f32x2_unpack(a6, a7, acc2[i][3]);
        float pel = a0 * alA.x + a1 * alA.y + a2 * alA.z + a3 * alA.w +
                    a4 * alB.x + a5 * alB.y + a6 * alB.z + a7 * alB.w;
        float per = a0 * arA.x + a1 * arA.y + a2 * arA.z + a3 * arA.w +
                    a4 * arB.x + a5 * arB.y + a6 * arB.z + a7 * arB.w;
        pel += __shfl_down_sync(0xffffffffu, pel, 1, 4);
        pel += __shfl_down_sync(0xffffffffu, pel, 2, 4);
        per += __shfl_down_sync(0xffffffffu, per, 1, 4);
        per += __shfl_down_sync(0xffffffffu, per, 2, 4);
        if (row < n) {
            __half2 h0 = __floats2half2_rn(a0, a1);
            __half2 h1 = __floats2half2_rn(a2, a3);
            __half2 h2 = __floats2half2_rn(a4, a5);
            __half2 h3 = __floats2half2_rn(a6, a7);
            uint4 pk;
            pk.x = *reinterpret_cast<unsigned*>(&h0);
            pk.y = *reinterpret_cast<unsigned*>(&h1);
            pk.z = *reinterpret_cast<unsigned*>(&h2);
            pk.w = *reinterpret_cast<unsigned*>(&h3);
            g_hh[row * 16 + tx] = pk;
            if ((tx & 3) == 0) {
                g_el[row * 4 + (tx >> 2)] = pel;
                g_er[row * 4 + (tx >> 2)] = per;
            }
        }
    }
}

// ---------------------------------------------------------------------------
// Single-pass softmax-aggregate + residual + bias + ELU.  Warp per dst node,
// TWO edges per iteration: lanes 0-15 -> edge i, lanes 16-31 -> edge i+1;
// each lane owns 8 features (one uint4) of its edge's h row.
// ---------------------------------------------------------------------------
__device__ __forceinline__ float lrelu(float x) { return x > 0.f ? x : 0.2f * x; }

__global__ __launch_bounds__(256) void agg_kernel(
    const float* prev_ext, const float* __restrict__ bias, int n, int use_act) {
    int w = (blockIdx.x * blockDim.x + threadIdx.x) >> 5;
    if (w >= n) return;
    const float* prev = use_act ? (const float*)g_act : prev_ext;
    int lane = threadIdx.x & 31;
    int sub = lane >> 4;       // which edge of the pair
    int fl = lane & 15;        // feature group: feats fl*8 .. fl*8+7
    int head = fl >> 2;
    int e0 = g_off[w];
    int e1 = g_off[w + 1];

    float erh = __ldg(&g_er[w * 4 + head]);

    const uint4* hp = (const uint4*)g_hh;
    float s = 0.f;
    unsigned long long acc2[4] = {0ull, 0ull, 0ull, 0ull};
#pragma unroll 4
    for (int i = e0; i < e1; i += 2) {
        int idx = i + sub;
        bool valid = idx < e1;
        int sn = __ldg(&g_csrc[valid ? idx : i]);
        float e = lrelu(__ldg(&g_el[sn * 4 + head]) + erh);
        float p = valid ? __expf(e) : 0.f;
        s += p;
        uint4 raw = __ldg(&hp[sn * 16 + fl]);
        unsigned long long pp = f32x2_pack(p, p);
        float2 f0 = __half22float2(*reinterpret_cast<const __half2*>(&raw.x));
        float2 f1 = __half22float2(*reinterpret_cast<const __half2*>(&raw.y));
        float2 f2 = __half22float2(*reinterpret_cast<const __half2*>(&raw.z));
        float2 f3 = __half22float2(*reinterpret_cast<const __half2*>(&raw.w));
        acc2[0] = f32x2_fma(pp, f32x2_pack(f0.x, f0.y), acc2[0]);
        acc2[1] = f32x2_fma(pp, f32x2_pack(f1.x, f1.y), acc2[1]);
        acc2[2] = f32x2_fma(pp, f32x2_pack(f2.x, f2.y), acc2[2]);
        acc2[3] = f32x2_fma(pp, f32x2_pack(f3.x, f3.y), acc2[3]);
    }
    // fold the two edge-subsets (lane L and L+16 hold the same feature slots)
    s += __shfl_xor_sync(0xffffffffu, s, 16);
    float a[8];
    f32x2_unpack(a[0], a[1], acc2[0]);
    f32x2_unpack(a[2], a[3], acc2[1]);
    f32x2_unpack(a[4], a[5], acc2[2]);
    f32x2_unpack(a[6], a[7], acc2[3]);
#pragma unroll
    for (int j = 0; j < 8; j++)
        a[j] += __shfl_xor_sync(0xffffffffu, a[j], 16);
    float inv = s > 0.f ? 1.f / s : 0.f;

    if (sub == 0) {
        float4 r0 = ((const float4*)prev)[w * 32 + fl * 2];
        float4 r1 = ((const float4*)prev)[w * 32 + fl * 2 + 1];
        float4 b0 = ((const float4*)bias)[fl * 2];
        float4 b1 = ((const float4*)bias)[fl * 2 + 1];
        float o0 = a[0] * inv + r0.x + b0.x;
        float o1 = a[1] * inv + r0.y + b0.y;
        float o2 = a[2] * inv + r0.z + b0.z;
        float o3 = a[3] * inv + r0.w + b0.w;
        float o4 = a[4] * inv + r1.x + b1.x;
        float o5 = a[5] * inv + r1.y + b1.y;
        float o6 = a[6] * inv + r1.z + b1.z;
        float o7 = a[7] * inv + r1.w + b1.w;
        o0 = o0 > 0.f ? o0 : expm1f(o0);
        o1 = o1 > 0.f ? o1 : expm1f(o1);
        o2 = o2 > 0.f ? o2 : expm1f(o2);
        o3 = o3 > 0.f ? o3 : expm1f(o3);
        o4 = o4 > 0.f ? o4 : expm1f(o4);
        o5 = o5 > 0.f ? o5 : expm1f(o5);
        o6 = o6 > 0.f ? o6 : expm1f(o6);
        o7 = o7 > 0.f ? o7 : expm1f(o7);
        ((float4*)g_act)[w * 32 + fl * 2]     = make_float4(o0, o1, o2, o3);
        ((float4*)g_act)[w * 32 + fl * 2 + 1] = make_float4(o4, o5, o6, o7);
    }
}

// ---------------------------------------------------------------------------
// Layer 4: h4 = act@W4 [N,2], res4 = act@Wres4 [N,2], el4/er4. Warp per row.
// ---------------------------------------------------------------------------
__global__ __launch_bounds__(256) void gemv4_kernel(
    const float* __restrict__ W4, const float* __restrict__ Wres4,
    const float* __restrict__ al4, const float* __restrict__ ar4, int n) {
    int w = (blockIdx.x * blockDim.x + threadIdx.x) >> 5;
    if (w >= n) return;
    int lane = threadIdx.x & 31;
    float4 xv = ((const float4*)g_act)[w * 32 + lane];
    float4 w0 = ((const float4*)W4)[lane * 2];
    float4 w1 = ((const float4*)W4)[lane * 2 + 1];
    float4 r0 = ((const float4*)Wres4)[lane * 2];
    float4 r1 = ((const float4*)Wres4)[lane * 2 + 1];
    float h0 = xv.x * w0.x + xv.y * w0.z + xv.z * w1.x + xv.w * w1.z;
    float h1 = xv.x * w0.y + xv.y * w0.w + xv.z * w1.y + xv.w * w1.w;
    float q0 = xv.x * r0.x + xv.y * r0.z + xv.z * r1.x + xv.w * r1.z;
    float q1 = xv.x * r0.y + xv.y * r0.w + xv.z * r1.y + xv.w * r1.w;
#pragma unroll
    for (int o = 16; o; o >>= 1) {
        h0 += __shfl_xor_sync(0xffffffffu, h0, o);
        h1 += __shfl_xor_sync(0xffffffffu, h1, o);
        q0 += __shfl_xor_sync(0xffffffffu, q0, o);
        q1 += __shfl_xor_sync(0xffffffffu, q1, o);
    }
    if (lane == 0) {
        g_h4[w * 2] = h0;
        g_h4[w * 2 + 1] = h1;
        g_res4[w * 2] = q0;
        g_res4[w * 2 + 1] = q1;
        g_el4[w] = h0 * al4[0] + h1 * al4[1];
        g_er4[w] = h0 * ar4[0] + h1 * ar4[1];
    }
}

// Single-pass layer-4 aggregation: lanes stride edges, one warp reduction.
__global__ __launch_bounds__(256) void agg4_kernel(
    const float* __restrict__ b4, float* __restrict__ out, int n) {
    int w = (blockIdx.x * blockDim.x + threadIdx.x) >> 5;
    if (w >= n) return;
    int lane = threadIdx.x & 31;
    int e0 = g_off[w];
    int e1 = g_off[w + 1];
    float erv = g_er4[w];

    float s = 0.f, a0 = 0.f, a1 = 0.f;
    for (int i = e0 + lane; i < e1; i += 32) {
        int sn = g_csrc[i];
        float e = lrelu(g_el4[sn] + erv);
        float p = __expf(e);
        s += p;
        float2 hv = ((const float2*)g_h4)[sn];
        a0 += p * hv.x;
        a1 += p * hv.y;
    }
#pragma unroll
    for (int o = 16; o; o >>= 1) {
        s  += __shfl_xor_sync(0xffffffffu, s, o);
        a0 += __shfl_xor_sync(0xffffffffu, a0, o);
        a1 += __shfl_xor_sync(0xffffffffu, a1, o);
    }
    float inv = s > 0.f ? 1.f / s : 0.f;
    if (lane == 0) {
        out[w * 2]     = a0 * inv + g_res4[w * 2]     + b4[0];
        out[w * 2 + 1] = a1 * inv + g_res4[w * 2 + 1] + b4[1];
    }
}

// ---------------------------------------------------------------------------
// Default-priority constructor: EAGER loading + context + full prewarm with
// VALID dummy pointers (cudaGetSymbolAddress — query only, no allocation).
// ---------------------------------------------------------------------------
namespace {
struct Prewarm {
    Prewarm() {
        setenv("CUDA_MODULE_LOADING", "EAGER", 1);  // before any CUDA call
        cudaFree(0);  // context creation -> eager module load

        void* ph = nullptr;
        void* pd = nullptr;
        cudaGetSymbolAddress(&ph, g_act);
        cudaGetSymbolAddress(&pd, g_deg);
        const float* fp = (const float*)ph;
        const int*   ip = (const int*)pd;
        float*       op = (float*)ph;

        int nbn = (MAXN + 255) / 256;
        int nbe = (MAXE + 255) / 256;
        int nbw = (MAXN + 7) / 8;
        int nbg = (MAXN + 127) / 128;
        int nbs = (MAXN + 1023) / 1024;
        long tot = (long)MAXN * 128;
        int nbt = (int)((tot + 255) / 256);

        touch_kernel<<<nbt, 256>>>();
        zero_kernel<<<nbn, 256>>>(0);
        hist_kernel<<<nbe, 256>>>(ip, 0);
        scan1_kernel<<<nbs, 1024>>>(0);
        scan2_kernel<<<1, 128>>>(0, 0);
        scan3_kernel<<<nbn, 256>>>(0);
        scatter_kernel<<<nbe, 256>>>(ip, ip, 0);
        gemm128_kernel<<<nbg, 256>>>(fp, fp, fp, fp, 0, 1);
        agg_kernel<<<nbw, 256>>>(fp, fp, 0, 1);
        gemv4_kernel<<<nbw, 256>>>(fp, fp, fp, fp, 0);
        agg4_kernel<<<nbw, 256>>>(fp, op, 0);
        touch_kernel<<<nbt, 256>>>();
        cudaDeviceSynchronize();
    }
};
Prewarm g_prewarm;
}  // namespace

// ---------------------------------------------------------------------------
// Launch: pure kernel launches, nothing else.
// ---------------------------------------------------------------------------
extern "C" void kernel_launch(void* const* d_in, const int* in_sizes, int n_in,
                              void* d_out, int out_size) {
    const float* x     = (const float*)d_in[0];
    const int*   src   = (const int*)d_in[1];
    const int*   dst   = (const int*)d_in[2];
    const float* W1    = (const float*)d_in[3];
    const float* al1   = (const float*)d_in[4];
    const float* ar1   = (const float*)d_in[5];
    const float* b1    = (const float*)d_in[6];
    const float* W2    = (const float*)d_in[7];
    const float* al2   = (const float*)d_in[8];
    const float* ar2   = (const float*)d_in[9];
    const float* b2    = (const float*)d_in[10];
    const float* W3    = (const float*)d_in[11];
    const float* al3   = (const float*)d_in[12];
    const float* ar3   = (const float*)d_in[13];
    const float* b3    = (const float*)d_in[14];
    const float* W4    = (const float*)d_in[15];
    const float* al4   = (const float*)d_in[16];
    const float* ar4   = (const float*)d_in[17];
    const float* b4    = (const float*)d_in[18];
    const float* Wres4 = (const float*)d_in[19];
    float* out = (float*)d_out;

    int n = in_sizes[0] / 128;
    int e = in_sizes[1];
    int nb = (n + 1023) / 1024;

    // CSR build (shared by all 4 layers)
    zero_kernel<<<(n + 255) / 256, 256>>>(n);
    hist_kernel<<<(e + 255) / 256, 256>>>(dst, e);
    scan1_kernel<<<nb, 1024>>>(n);
    scan2_kernel<<<1, 128>>>(nb, n);
    scan3_kernel<<<(n + 255) / 256, 256>>>(n);
    scatter_kernel<<<(e + 255) / 256, 256>>>(src, dst, e);

    int nbw = (n + 7) / 8;        // warp-per-node grids
    int nbg = (n + 127) / 128;    // gemm grid (BM=128)

    // layer 1: x -> g_act
    gemm128_kernel<<<nbg, 256>>>(x, W1, al1, ar1, n, 0);
    agg_kernel<<<nbw, 256>>>(x, b1, n, 0);

    // layer 2: g_act -> g_act (in place)
    gemm128_kernel<<<nbg, 256>>>(nullptr, W2, al2, ar2, n, 1);
    agg_kernel<<<nbw, 256>>>(nullptr, b2, n, 1);

    // layer 3: g_act -> g_act (in place)
    gemm128_kernel<<<nbg, 256>>>(nullptr, W3, al3, ar3, n, 1);
    agg_kernel<<<nbw, 256>>>(nullptr, b3, n, 1);

    // layer 4: g_act -> out
    gemv4_kernel<<<nbw, 256>>>(W4, Wres4, al4, ar4, n);
    agg4_kernel<<<nbw, 256>>>(b4, out, n);
}

// round 11
// speedup vs baseline: 1.0760x; 1.0760x over previous
#include <cuda_runtime.h>
#include <cuda_fp16.h>
#include <math.h>
#include <stdint.h>
#include <stdlib.h>

// ---------------------------------------------------------------------------
// GAT 4-layer forward.  N=100000, E=1600000, 128 feats (4h x 32d).
// R11: agg reverted to the R9 single-edge form (R10's 2-edge variant lost
// occupancy to register pressure and regressed).  NEW: the CSR build runs on
// a forked capture stream concurrently with the layer-1 GEMM; they join
// before agg1.  GEMM (FFMA2, BM=128) unchanged.
// ---------------------------------------------------------------------------

#define MAXN 100000
#define MAXE 1600000

__device__ uint4 g_hh[MAXN * 16];     // projected features, fp16 (256B/row)
__device__ float g_act[MAXN * 128];   // activations (updated in place)
__device__ float g_el[MAXN * 4];
__device__ float g_er[MAXN * 4];
__device__ int   g_deg[MAXN];
__device__ int   g_cur[MAXN];
__device__ int   g_off[MAXN + 1];
__device__ int   g_csrc[MAXE];
__device__ int   g_bsum[128];
__device__ int   g_boff[128];
__device__ float g_h4[MAXN * 2];
__device__ float g_res4[MAXN * 2];
__device__ float g_el4[MAXN];
__device__ float g_er4[MAXN];

// ---- f32x2 helpers --------------------------------------------------------
__device__ __forceinline__ unsigned long long f32x2_pack(float a, float b) {
    unsigned long long d;
    asm("mov.b64 %0, {%1, %2};" : "=l"(d) : "f"(a), "f"(b));
    return d;
}
__device__ __forceinline__ void f32x2_unpack(float& a, float& b,
                                             unsigned long long v) {
    asm("mov.b64 {%0, %1}, %2;" : "=f"(a), "=f"(b) : "l"(v));
}
__device__ __forceinline__ unsigned long long f32x2_fma(
    unsigned long long a, unsigned long long b, unsigned long long c) {
    unsigned long long d;
    asm("fma.rn.f32x2 %0, %1, %2, %3;" : "=l"(d) : "l"(a), "l"(b), "l"(c));
    return d;
}

// ---------------------------------------------------------------------------
// CSR build
// ---------------------------------------------------------------------------
__global__ void zero_kernel(int n) {
    int i = blockIdx.x * blockDim.x + threadIdx.x;
    if (i < n) { g_deg[i] = 0; g_cur[i] = 0; }
}

__global__ void hist_kernel(const int* __restrict__ dst, int e) {
    int i = blockIdx.x * blockDim.x + threadIdx.x;
    if (i < e) atomicAdd(&g_deg[dst[i]], 1);
}

__global__ void scan1_kernel(int n) {
    __shared__ int sm[1024];
    int t = threadIdx.x;
    int i = blockIdx.x * 1024 + t;
    int v = (i < n) ? g_deg[i] : 0;
    sm[t] = v;
    __syncthreads();
    for (int o = 1; o < 1024; o <<= 1) {
        int u = (t >= o) ? sm[t - o] : 0;
        __syncthreads();
        sm[t] += u;
        __syncthreads();
    }
    if (i < n) g_off[i] = sm[t] - v;   // exclusive within block
    if (t == 1023) g_bsum[blockIdx.x] = sm[1023];
}

__global__ void scan2_kernel(int nb, int n) {
    __shared__ int sm[128];
    int t = threadIdx.x;
    int v = (t < nb) ? g_bsum[t] : 0;
    sm[t] = v;
    __syncthreads();
    for (int o = 1; o < 128; o <<= 1) {
        int u = (t >= o) ? sm[t - o] : 0;
        __syncthreads();
        sm[t] += u;
        __syncthreads();
    }
    if (t < nb) g_boff[t] = sm[t] - v;
    if (t == 127) g_off[n] = sm[127];  // total edge count
}

__global__ void scan3_kernel(int n) {
    int i = blockIdx.x * blockDim.x + threadIdx.x;
    if (i < n) g_off[i] += g_boff[i >> 10];
}

__global__ void scatter_kernel(const int* __restrict__ src,
                               const int* __restrict__ dst, int e) {
    int i = blockIdx.x * blockDim.x + threadIdx.x;
    if (i < e) {
        int d = dst[i];
        int pos = atomicAdd(&g_cur[d], 1);
        g_csrc[g_off[d] + pos] = src[i];
    }
}

// ---------------------------------------------------------------------------
// Touch kernel (prewarm only): commit all big globals.
// ---------------------------------------------------------------------------
__global__ void touch_kernel() {
    long i = (long)blockIdx.x * blockDim.x + threadIdx.x;
    long tot = (long)MAXN * 128;
    if (i < (long)MAXN * 16) g_hh[i] = make_uint4(0, 0, 0, 0);
    if (i < tot) g_act[i] = 0.f;
    if (i < MAXE) g_csrc[i] = 0;
    if (i < MAXN) {
        g_el[i * 4] = 0.f; g_er[i * 4] = 0.f;
        g_el4[i] = 0.f; g_er4[i] = 0.f;
        g_h4[i * 2] = 0.f; g_res4[i * 2] = 0.f;
        g_deg[i] = 0; g_cur[i] = 0; g_off[i] = 0;
    }
    if (i < 128) { g_bsum[i] = 0; g_boff[i] = 0; }
}

// ---------------------------------------------------------------------------
// GEMM: g_hh[n,128](fp16) = X[n,128] @ W[128,128]; epilogue computes el/er.
// BM=128, 256 threads (16x16), per-thread 8x8 tile as f32x2 pairs (FFMA2).
// ---------------------------------------------------------------------------
__global__ __launch_bounds__(256, 2) void gemm128_kernel(
    const float* __restrict__ X_ext, const float* __restrict__ W,
    const float* __restrict__ al, const float* __restrict__ ar,
    int n, int use_act) {
    const float* X = use_act ? (const float*)g_act : X_ext;
    __shared__ float Xs[32][132];  // [k][row], padded
    __shared__ float Ws[32][132];  // [k][col], padded

    int tid = threadIdx.x;
    int tx = tid & 15;   // col group: cols tx*8 .. tx*8+7 (head = tx>>2)
    int ty = tid >> 4;   // row group: rows ty*8 .. ty*8+7
    int row0 = blockIdx.x * 128;

    unsigned long long acc2[8][4];
#pragma unroll
    for (int i = 0; i < 8; i++)
#pragma unroll
        for (int j = 0; j < 4; j++) acc2[i][j] = 0ull;

    for (int kc = 0; kc < 128; kc += 32) {
        // X tile: 128 rows x 32 k, transposed into Xs[k][row]
#pragma unroll
        for (int i = tid; i < 128 * 8; i += 256) {
            int r = i >> 3;
            int kq = i & 7;
            int row = row0 + r;
            float4 v = make_float4(0.f, 0.f, 0.f, 0.f);
            if (row < n) v = ((const float4*)X)[row * 32 + (kc >> 2) + kq];
            Xs[kq * 4 + 0][r] = v.x;
            Xs[kq * 4 + 1][r] = v.y;
            Xs[kq * 4 + 2][r] = v.z;
            Xs[kq * 4 + 3][r] = v.w;
        }
        // W tile: 32 k x 128 cols
#pragma unroll
        for (int i = tid; i < 32 * 32; i += 256) {
            int k = i >> 5;
            int cq = i & 31;
            float4 v = ((const float4*)W)[(kc + k) * 32 + cq];
            *(float4*)&Ws[k][cq * 4] = v;
        }
        __syncthreads();

#pragma unroll
        for (int kk = 0; kk < 32; kk++) {
            float4 xa = *(const float4*)&Xs[kk][ty * 8];
            float4 xb = *(const float4*)&Xs[kk][ty * 8 + 4];
            float4 wa = *(const float4*)&Ws[kk][tx * 8];
            float4 wb = *(const float4*)&Ws[kk][tx * 8 + 4];
            unsigned long long wp[4];
            wp[0] = f32x2_pack(wa.x, wa.y);
            wp[1] = f32x2_pack(wa.z, wa.w);
            wp[2] = f32x2_pack(wb.x, wb.y);
            wp[3] = f32x2_pack(wb.z, wb.w);
            float xr[8] = {xa.x, xa.y, xa.z, xa.w, xb.x, xb.y, xb.z, xb.w};
#pragma unroll
            for (int i = 0; i < 8; i++) {
                unsigned long long xd = f32x2_pack(xr[i], xr[i]);
#pragma unroll
                for (int j = 0; j < 4; j++)
                    acc2[i][j] = f32x2_fma(xd, wp[j], acc2[i][j]);
            }
        }
        __syncthreads();
    }

    // epilogue: fp16 h + fused el/er (this thread's 8 cols lie in head tx>>2)
    float4 alA = ((const float4*)al)[tx * 2];
    float4 alB = ((const float4*)al)[tx * 2 + 1];
    float4 arA = ((const float4*)ar)[tx * 2];
    float4 arB = ((const float4*)ar)[tx * 2 + 1];
#pragma unroll
    for (int i = 0; i < 8; i++) {
        int row = row0 + ty * 8 + i;
        float a0, a1, a2, a3, a4, a5, a6, a7;
        f32x2_unpack(a0, a1, acc2[i][0]);
        f32x2_unpack(a2, a3, acc2[i][1]);
        f32x2_unpack(a4, a5, acc2[i][2]);
        f32x2_unpack(a6, a7, acc2[i][3]);
        float pel = a0 * alA.x + a1 * alA.y + a2 * alA.z + a3 * alA.w +
                    a4 * alB.x + a5 * alB.y + a6 * alB.z + a7 * alB.w;
        float per = a0 * arA.x + a1 * arA.y + a2 * arA.z + a3 * arA.w +
                    a4 * arB.x + a5 * arB.y + a6 * arB.z + a7 * arB.w;
        pel += __shfl_down_sync(0xffffffffu, pel, 1, 4);
        pel += __shfl_down_sync(0xffffffffu, pel, 2, 4);
        per += __shfl_down_sync(0xffffffffu, per, 1, 4);
        per += __shfl_down_sync(0xffffffffu, per, 2, 4);
        if (row < n) {
            __half2 h0 = __floats2half2_rn(a0, a1);
            __half2 h1 = __floats2half2_rn(a2, a3);
            __half2 h2 = __floats2half2_rn(a4, a5);
            __half2 h3 = __floats2half2_rn(a6, a7);
            uint4 pk;
            pk.x = *reinterpret_cast<unsigned*>(&h0);
            pk.y = *reinterpret_cast<unsigned*>(&h1);
            pk.z = *reinterpret_cast<unsigned*>(&h2);
            pk.w = *reinterpret_cast<unsigned*>(&h3);
            g_hh[row * 16 + tx] = pk;
            if ((tx & 3) == 0) {
                g_el[row * 4 + (tx >> 2)] = pel;
                g_er[row * 4 + (tx >> 2)] = per;
            }
        }
    }
}

// ---------------------------------------------------------------------------
// Single-pass softmax-aggregate + residual + bias + ELU.  Warp per dst node.
// (R9 form: one edge per iteration, uint2 per lane, unroll 4.)
// ---------------------------------------------------------------------------
__device__ __forceinline__ float lrelu(float x) { return x > 0.f ? x : 0.2f * x; }

__global__ __launch_bounds__(256) void agg_kernel(
    const float* prev_ext, const float* __restrict__ bias, int n, int use_act) {
    int w = (blockIdx.x * blockDim.x + threadIdx.x) >> 5;
    if (w >= n) return;
    const float* prev = use_act ? (const float*)g_act : prev_ext;
    int lane = threadIdx.x & 31;
    int head = lane >> 3;
    int e0 = g_off[w];
    int e1 = g_off[w + 1];

    float erh = __ldg(&g_er[w * 4 + head]);

    const uint2* hp = (const uint2*)g_hh;
    float s = 0.f;
    float4 acc = make_float4(0.f, 0.f, 0.f, 0.f);
#pragma unroll 4
    for (int i = e0; i < e1; ++i) {
        int sn = __ldg(&g_csrc[i]);
        float e = lrelu(__ldg(&g_el[sn * 4 + head]) + erh);
        float p = __expf(e);
        s += p;
        uint2 raw = __ldg(&hp[sn * 32 + lane]);
        __half2 ha = *reinterpret_cast<const __half2*>(&raw.x);
        __half2 hb = *reinterpret_cast<const __half2*>(&raw.y);
        float2 f01 = __half22float2(ha);
        float2 f23 = __half22float2(hb);
        acc.x += p * f01.x;
        acc.y += p * f01.y;
        acc.z += p * f23.x;
        acc.w += p * f23.y;
    }
    float inv = s > 0.f ? 1.f / s : 0.f;

    float4 r = ((const float4*)prev)[w * 32 + lane];
    float4 bb = ((const float4*)bias)[lane];
    float o0 = acc.x * inv + r.x + bb.x;
    float o1 = acc.y * inv + r.y + bb.y;
    float o2 = acc.z * inv + r.z + bb.z;
    float o3 = acc.w * inv + r.w + bb.w;
    o0 = o0 > 0.f ? o0 : expm1f(o0);
    o1 = o1 > 0.f ? o1 : expm1f(o1);
    o2 = o2 > 0.f ? o2 : expm1f(o2);
    o3 = o3 > 0.f ? o3 : expm1f(o3);
    ((float4*)g_act)[w * 32 + lane] = make_float4(o0, o1, o2, o3);
}

// ---------------------------------------------------------------------------
// Layer 4: h4 = act@W4 [N,2], res4 = act@Wres4 [N,2], el4/er4. Warp per row.
// ---------------------------------------------------------------------------
__global__ __launch_bounds__(256) void gemv4_kernel(
    const float* __restrict__ W4, const float* __restrict__ Wres4,
    const float* __restrict__ al4, const float* __restrict__ ar4, int n) {
    int w = (blockIdx.x * blockDim.x + threadIdx.x) >> 5;
    if (w >= n) return;
    int lane = threadIdx.x & 31;
    float4 xv = ((const float4*)g_act)[w * 32 + lane];
    float4 w0 = ((const float4*)W4)[lane * 2];
    float4 w1 = ((const float4*)W4)[lane * 2 + 1];
    float4 r0 = ((const float4*)Wres4)[lane * 2];
    float4 r1 = ((const float4*)Wres4)[lane * 2 + 1];
    float h0 = xv.x * w0.x + xv.y * w0.z + xv.z * w1.x + xv.w * w1.z;
    float h1 = xv.x * w0.y + xv.y * w0.w + xv.z * w1.y + xv.w * w1.w;
    float q0 = xv.x * r0.x + xv.y * r0.z + xv.z * r1.x + xv.w * r1.z;
    float q1 = xv.x * r0.y + xv.y * r0.w + xv.z * r1.y + xv.w * r1.w;
#pragma unroll
    for (int o = 16; o; o >>= 1) {
        h0 += __shfl_xor_sync(0xffffffffu, h0, o);
        h1 += __shfl_xor_sync(0xffffffffu, h1, o);
        q0 += __shfl_xor_sync(0xffffffffu, q0, o);
        q1 += __shfl_xor_sync(0xffffffffu, q1, o);
    }
    if (lane == 0) {
        g_h4[w * 2] = h0;
        g_h4[w * 2 + 1] = h1;
        g_res4[w * 2] = q0;
        g_res4[w * 2 + 1] = q1;
        g_el4[w] = h0 * al4[0] + h1 * al4[1];
        g_er4[w] = h0 * ar4[0] + h1 * ar4[1];
    }
}

// Single-pass layer-4 aggregation: lanes stride edges, one warp reduction.
__global__ __launch_bounds__(256) void agg4_kernel(
    const float* __restrict__ b4, float* __restrict__ out, int n) {
    int w = (blockIdx.x * blockDim.x + threadIdx.x) >> 5;
    if (w >= n) return;
    int lane = threadIdx.x & 31;
    int e0 = g_off[w];
    int e1 = g_off[w + 1];
    float erv = g_er4[w];

    float s = 0.f, a0 = 0.f, a1 = 0.f;
    for (int i = e0 + lane; i < e1; i += 32) {
        int sn = g_csrc[i];
        float e = lrelu(g_el4[sn] + erv);
        float p = __expf(e);
        s += p;
        float2 hv = ((const float2*)g_h4)[sn];
        a0 += p * hv.x;
        a1 += p * hv.y;
    }
#pragma unroll
    for (int o = 16; o; o >>= 1) {
        s  += __shfl_xor_sync(0xffffffffu, s, o);
        a0 += __shfl_xor_sync(0xffffffffu, a0, o);
        a1 += __shfl_xor_sync(0xffffffffu, a1, o);
    }
    float inv = s > 0.f ? 1.f / s : 0.f;
    if (lane == 0) {
        out[w * 2]     = a0 * inv + g_res4[w * 2]     + b4[0];
        out[w * 2 + 1] = a1 * inv + g_res4[w * 2 + 1] + b4[1];
    }
}

// ---------------------------------------------------------------------------
// Constructor: EAGER loading, context, prewarm, and the aux stream + events
// used to overlap the CSR build with the layer-1 GEMM during capture.
// ---------------------------------------------------------------------------
namespace {
cudaStream_t g_saux;
cudaEvent_t  g_ev_fork;
cudaEvent_t  g_ev_join;

struct Prewarm {
    Prewarm() {
        setenv("CUDA_MODULE_LOADING", "EAGER", 1);  // before any CUDA call
        cudaFree(0);  // context creation -> eager module load

        cudaStreamCreateWithFlags(&g_saux, cudaStreamNonBlocking);
        cudaEventCreateWithFlags(&g_ev_fork, cudaEventDisableTiming);
        cudaEventCreateWithFlags(&g_ev_join, cudaEventDisableTiming);

        void* ph = nullptr;
        void* pd = nullptr;
        cudaGetSymbolAddress(&ph, g_act);
        cudaGetSymbolAddress(&pd, g_deg);
        const float* fp = (const float*)ph;
        const int*   ip = (const int*)pd;
        float*       op = (float*)ph;

        int nbn = (MAXN + 255) / 256;
        int nbe = (MAXE + 255) / 256;
        int nbw = (MAXN + 7) / 8;
        int nbg = (MAXN + 127) / 128;
        int nbs = (MAXN + 1023) / 1024;
        long tot = (long)MAXN * 128;
        int nbt = (int)((tot + 255) / 256);

        touch_kernel<<<nbt, 256>>>();
        zero_kernel<<<nbn, 256>>>(0);
        hist_kernel<<<nbe, 256>>>(ip, 0);
        scan1_kernel<<<nbs, 1024>>>(0);
        scan2_kernel<<<1, 128>>>(0, 0);
        scan3_kernel<<<nbn, 256>>>(0);
        scatter_kernel<<<nbe, 256>>>(ip, ip, 0);
        gemm128_kernel<<<nbg, 256>>>(fp, fp, fp, fp, 0, 1);
        agg_kernel<<<nbw, 256>>>(fp, fp, 0, 1);
        gemv4_kernel<<<nbw, 256>>>(fp, fp, fp, fp, 0);
        agg4_kernel<<<nbw, 256>>>(fp, op, 0);
        // also prewarm kernels on the aux stream
        zero_kernel<<<nbn, 256, 0, g_saux>>>(0);
        touch_kernel<<<nbt, 256>>>();
        cudaDeviceSynchronize();
    }
};
Prewarm g_prewarm;
}  // namespace

// ---------------------------------------------------------------------------
// Launch: pure kernel launches + event fork/join (capture-legal).
// CSR build runs on g_saux concurrently with the layer-1 GEMM.
// ---------------------------------------------------------------------------
extern "C" void kernel_launch(void* const* d_in, const int* in_sizes, int n_in,
                              void* d_out, int out_size) {
    const float* x     = (const float*)d_in[0];
    const int*   src   = (const int*)d_in[1];
    const int*   dst   = (const int*)d_in[2];
    const float* W1    = (const float*)d_in[3];
    const float* al1   = (const float*)d_in[4];
    const float* ar1   = (const float*)d_in[5];
    const float* b1    = (const float*)d_in[6];
    const float* W2    = (const float*)d_in[7];
    const float* al2   = (const float*)d_in[8];
    const float* ar2   = (const float*)d_in[9];
    const float* b2    = (const float*)d_in[10];
    const float* W3    = (const float*)d_in[11];
    const float* al3   = (const float*)d_in[12];
    const float* ar3   = (const float*)d_in[13];
    const float* b3    = (const float*)d_in[14];
    const float* W4    = (const float*)d_in[15];
    const float* al4   = (const float*)d_in[16];
    const float* ar4   = (const float*)d_in[17];
    const float* b4    = (const float*)d_in[18];
    const float* Wres4 = (const float*)d_in[19];
    float* out = (float*)d_out;

    int n = in_sizes[0] / 128;
    int e = in_sizes[1];
    int nb = (n + 1023) / 1024;

    int nbw = (n + 7) / 8;        // warp-per-node grids
    int nbg = (n + 127) / 128;    // gemm grid (BM=128)

    // Fork: CSR build on aux stream, layer-1 GEMM on main stream.
    cudaEventRecord(g_ev_fork, 0);
    cudaStreamWaitEvent(g_saux, g_ev_fork, 0);

    zero_kernel<<<(n + 255) / 256, 256, 0, g_saux>>>(n);
    hist_kernel<<<(e + 255) / 256, 256, 0, g_saux>>>(dst, e);
    scan1_kernel<<<nb, 1024, 0, g_saux>>>(n);
    scan2_kernel<<<1, 128, 0, g_saux>>>(nb, n);
    scan3_kernel<<<(n + 255) / 256, 256, 0, g_saux>>>(n);
    scatter_kernel<<<(e + 255) / 256, 256, 0, g_saux>>>(src, dst, e);
    cudaEventRecord(g_ev_join, g_saux);

    gemm128_kernel<<<nbg, 256>>>(x, W1, al1, ar1, n, 0);

    // Join: agg1 needs both CSR and GEMM1.
    cudaStreamWaitEvent(0, g_ev_join, 0);
    agg_kernel<<<nbw, 256>>>(x, b1, n, 0);

    // layer 2: g_act -> g_act (in place)
    gemm128_kernel<<<nbg, 256>>>(nullptr, W2, al2, ar2, n, 1);
    agg_kernel<<<nbw, 256>>>(nullptr, b2, n, 1);

    // layer 3: g_act -> g_act (in place)
    gemm128_kernel<<<nbg, 256>>>(nullptr, W3, al3, ar3, n, 1);
    agg_kernel<<<nbw, 256>>>(nullptr, b3, n, 1);

    // layer 4: g_act -> out
    gemv4_kernel<<<nbw, 256>>>(W4, Wres4, al4, ar4, n);
    agg4_kernel<<<nbw, 256>>>(b4, out, n);
}

// round 12
// speedup vs baseline: 1.2119x; 1.1264x over previous
#include <cuda_runtime.h>
#include <cuda_fp16.h>
#include <math.h>
#include <stdint.h>
#include <stdlib.h>

// ---------------------------------------------------------------------------
// GAT 4-layer forward.  N=100000, E=1600000, 128 feats (4h x 32d).
// R12: GEMM moved to tensor cores (mma.sync.m16n8k16 f32.f16.f16.f32).
// fp32 inputs converted to fp16 smem tiles; 8 warps x (16 rows x 128 cols)
// full-width warp tiles; C staged to smem fp16; epilogue writes g_hh and
// computes el/er with zero shuffles.  agg (R9 single-pass), CSR overlap,
// layer 4 unchanged.
// ---------------------------------------------------------------------------

#define MAXN 100000
#define MAXE 1600000

__device__ uint4 g_hh[MAXN * 16];     // projected features, fp16 (256B/row)
__device__ float g_act[MAXN * 128];   // activations (updated in place)
__device__ float g_el[MAXN * 4];
__device__ float g_er[MAXN * 4];
__device__ int   g_deg[MAXN];
__device__ int   g_cur[MAXN];
__device__ int   g_off[MAXN + 1];
__device__ int   g_csrc[MAXE];
__device__ int   g_bsum[128];
__device__ int   g_boff[128];
__device__ float g_h4[MAXN * 2];
__device__ float g_res4[MAXN * 2];
__device__ float g_el4[MAXN];
__device__ float g_er4[MAXN];

// ---------------------------------------------------------------------------
// CSR build
// ---------------------------------------------------------------------------
__global__ void zero_kernel(int n) {
    int i = blockIdx.x * blockDim.x + threadIdx.x;
    if (i < n) { g_deg[i] = 0; g_cur[i] = 0; }
}

__global__ void hist_kernel(const int* __restrict__ dst, int e) {
    int i = blockIdx.x * blockDim.x + threadIdx.x;
    if (i < e) atomicAdd(&g_deg[dst[i]], 1);
}

__global__ void scan1_kernel(int n) {
    __shared__ int sm[1024];
    int t = threadIdx.x;
    int i = blockIdx.x * 1024 + t;
    int v = (i < n) ? g_deg[i] : 0;
    sm[t] = v;
    __syncthreads();
    for (int o = 1; o < 1024; o <<= 1) {
        int u = (t >= o) ? sm[t - o] : 0;
        __syncthreads();
        sm[t] += u;
        __syncthreads();
    }
    if (i < n) g_off[i] = sm[t] - v;
    if (t == 1023) g_bsum[blockIdx.x] = sm[1023];
}

__global__ void scan2_kernel(int nb, int n) {
    __shared__ int sm[128];
    int t = threadIdx.x;
    int v = (t < nb) ? g_bsum[t] : 0;
    sm[t] = v;
    __syncthreads();
    for (int o = 1; o < 128; o <<= 1) {
        int u = (t >= o) ? sm[t - o] : 0;
        __syncthreads();
        sm[t] += u;
        __syncthreads();
    }
    if (t < nb) g_boff[t] = sm[t] - v;
    if (t == 127) g_off[n] = sm[127];
}

__global__ void scan3_kernel(int n) {
    int i = blockIdx.x * blockDim.x + threadIdx.x;
    if (i < n) g_off[i] += g_boff[i >> 10];
}

__global__ void scatter_kernel(const int* __restrict__ src,
                               const int* __restrict__ dst, int e) {
    int i = blockIdx.x * blockDim.x + threadIdx.x;
    if (i < e) {
        int d = dst[i];
        int pos = atomicAdd(&g_cur[d], 1);
        g_csrc[g_off[d] + pos] = src[i];
    }
}

// ---------------------------------------------------------------------------
// Touch kernel (prewarm only)
// ---------------------------------------------------------------------------
__global__ void touch_kernel() {
    long i = (long)blockIdx.x * blockDim.x + threadIdx.x;
    long tot = (long)MAXN * 128;
    if (i < (long)MAXN * 16) g_hh[i] = make_uint4(0, 0, 0, 0);
    if (i < tot) g_act[i] = 0.f;
    if (i < MAXE) g_csrc[i] = 0;
    if (i < MAXN) {
        g_el[i * 4] = 0.f; g_er[i * 4] = 0.f;
        g_el4[i] = 0.f; g_er4[i] = 0.f;
        g_h4[i * 2] = 0.f; g_res4[i * 2] = 0.f;
        g_deg[i] = 0; g_cur[i] = 0; g_off[i] = 0;
    }
    if (i < 128) { g_bsum[i] = 0; g_boff[i] = 0; }
}

// ---------------------------------------------------------------------------
// Tensor-core GEMM: g_hh[n,128](fp16) = X[n,128] @ W[128,128].
// BM=128, full K=128 in one stage.  8 warps, warp tile 16 rows x 128 cols.
// Epilogue (via smem C): h fp16 write + fused el/er.
// ---------------------------------------------------------------------------
#define ASTRIDE 136                       // halves per smem row (272B, odd 16B units)
#define SMEM_TC (2 * 128 * ASTRIDE * 2)   // A + B tiles, bytes

__global__ __launch_bounds__(256) void gemm_tc_kernel(
    const float* __restrict__ X_ext, const float* __restrict__ W,
    const float* __restrict__ al, const float* __restrict__ ar,
    int n, int use_act) {
    const float* X = use_act ? (const float*)g_act : X_ext;
    extern __shared__ __half sm[];
    __half* As = sm;                    // [128][ASTRIDE]
    __half* Bs = sm + 128 * ASTRIDE;    // [128][ASTRIDE] (k-major W)

    int tid = threadIdx.x;
    int lane = tid & 31;
    int wid = tid >> 5;
    int row0 = blockIdx.x * 128;

    // Load + convert A (X rows) and B (W) to fp16 smem.
    for (int i = tid; i < 128 * 32; i += 256) {
        int r = i >> 5;
        int kq = i & 31;
        int row = row0 + r;
        float4 v = make_float4(0.f, 0.f, 0.f, 0.f);
        if (row < n) v = ((const float4*)X)[row * 32 + kq];
        __half2 p0 = __floats2half2_rn(v.x, v.y);
        __half2 p1 = __floats2half2_rn(v.z, v.w);
        uint2 pk;
        pk.x = *reinterpret_cast<unsigned*>(&p0);
        pk.y = *reinterpret_cast<unsigned*>(&p1);
        *reinterpret_cast<uint2*>(&As[r * ASTRIDE + kq * 4]) = pk;
    }
    for (int i = tid; i < 128 * 32; i += 256) {
        int r = i >> 5;     // k index
        int kq = i & 31;    // col group
        float4 v = ((const float4*)W)[r * 32 + kq];
        __half2 p0 = __floats2half2_rn(v.x, v.y);
        __half2 p1 = __floats2half2_rn(v.z, v.w);
        uint2 pk;
        pk.x = *reinterpret_cast<unsigned*>(&p0);
        pk.y = *reinterpret_cast<unsigned*>(&p1);
        *reinterpret_cast<uint2*>(&Bs[r * ASTRIDE + kq * 4]) = pk;
    }
    __syncthreads();

    // MMA: warp wid owns rows [16*wid, 16*wid+16), all 128 cols (16 n-atoms).
    int mrow = wid * 16;
    int row_sel = lane & 15;            // ldmatrix row within 16
    int col_off8 = (lane >> 4) << 3;    // 0 or 8
    float c[16][4];
#pragma unroll
    for (int a = 0; a < 16; a++)
#pragma unroll
        for (int j = 0; j < 4; j++) c[a][j] = 0.f;

#pragma unroll
    for (int ks = 0; ks < 8; ks++) {
        unsigned a0, a1, a2, a3;
        {
            unsigned addr = (unsigned)__cvta_generic_to_shared(
                &As[(mrow + row_sel) * ASTRIDE + ks * 16 + col_off8]);
            asm volatile(
                "ldmatrix.sync.aligned.m8n8.x4.shared.b16 {%0,%1,%2,%3}, [%4];"
                : "=r"(a0), "=r"(a1), "=r"(a2), "=r"(a3) : "r"(addr));
        }
#pragma unroll
        for (int nb2 = 0; nb2 < 8; nb2++) {
            unsigned b0, b1, b2, b3;
            unsigned addr = (unsigned)__cvta_generic_to_shared(
                &Bs[(ks * 16 + row_sel) * ASTRIDE + nb2 * 16 + col_off8]);
            asm volatile(
                "ldmatrix.sync.aligned.m8n8.x4.trans.shared.b16 {%0,%1,%2,%3}, [%4];"
                : "=r"(b0), "=r"(b1), "=r"(b2), "=r"(b3) : "r"(addr));
            int na = nb2 * 2;
            asm volatile(
                "mma.sync.aligned.m16n8k16.row.col.f32.f16.f16.f32 "
                "{%0,%1,%2,%3}, {%4,%5,%6,%7}, {%8,%9}, {%0,%1,%2,%3};"
                : "+f"(c[na][0]), "+f"(c[na][1]), "+f"(c[na][2]), "+f"(c[na][3])
                : "r"(a0), "r"(a1), "r"(a2), "r"(a3), "r"(b0), "r"(b1));
            asm volatile(
                "mma.sync.aligned.m16n8k16.row.col.f32.f16.f16.f32 "
                "{%0,%1,%2,%3}, {%4,%5,%6,%7}, {%8,%9}, {%0,%1,%2,%3};"
                : "+f"(c[na + 1][0]), "+f"(c[na + 1][1]), "+f"(c[na + 1][2]), "+f"(c[na + 1][3])
                : "r"(a0), "r"(a1), "r"(a2), "r"(a3), "r"(b2), "r"(b3));
        }
    }
    __syncthreads();  // done reading As; reuse as C staging

    // Stage C (fp16) into As region: thread holds rows r0, r0+8; cols (lane&3)*2 (+1) per atom.
    {
        int r0 = mrow + (lane >> 2);
        int cc = (lane & 3) * 2;
#pragma unroll
        for (int na = 0; na < 16; na++) {
            __half2 lo = __floats2half2_rn(c[na][0], c[na][1]);
            __half2 hi = __floats2half2_rn(c[na][2], c[na][3]);
            *reinterpret_cast<unsigned*>(&As[r0 * ASTRIDE + na * 8 + cc]) =
                *reinterpret_cast<unsigned*>(&lo);
            *reinterpret_cast<unsigned*>(&As[(r0 + 8) * ASTRIDE + na * 8 + cc]) =
                *reinterpret_cast<unsigned*>(&hi);
        }
    }
    __syncthreads();

    // Epilogue: thread t handles row t>>1, half-row (t&1)*64 (heads 2*(t&1), +1).
    {
        int r = tid >> 1;
        int hsel = tid & 1;
        int row = row0 + r;
        if (row < n) {
            uint4 cv[8];
#pragma unroll
            for (int j = 0; j < 8; j++)
                cv[j] = *reinterpret_cast<uint4*>(&As[r * ASTRIDE + hsel * 64 + j * 8]);
            // write h
#pragma unroll
            for (int j = 0; j < 8; j++)
                g_hh[row * 16 + hsel * 8 + j] = cv[j];
            // el/er for the two heads in this half-row
            int h0 = hsel * 2;
            float el0 = 0.f, er0 = 0.f, el1 = 0.f, er1 = 0.f;
#pragma unroll
            for (int j = 0; j < 8; j++) {
                const __half2* hp = reinterpret_cast<const __half2*>(&cv[j]);
#pragma unroll
                for (int q = 0; q < 4; q++) {
                    float2 f = __half22float2(hp[q]);
                    int d = (j * 8 + q * 2) & 31;  // within-head feature index
                    if (j < 4) {
                        el0 += f.x * al[h0 * 32 + d]     + f.y * al[h0 * 32 + d + 1];
                        er0 += f.x * ar[h0 * 32 + d]     + f.y * ar[h0 * 32 + d + 1];
                    } else {
                        el1 += f.x * al[(h0 + 1) * 32 + d] + f.y * al[(h0 + 1) * 32 + d + 1];
                        er1 += f.x * ar[(h0 + 1) * 32 + d] + f.y * ar[(h0 + 1) * 32 + d + 1];
                    }
                }
            }
            float2 elv = make_float2(el0, el1);
            float2 erv = make_float2(er0, er1);
            *reinterpret_cast<float2*>(&g_el[row * 4 + h0]) = elv;
            *reinterpret_cast<float2*>(&g_er[row * 4 + h0]) = erv;
        }
    }
}

// ---------------------------------------------------------------------------
// Single-pass softmax-aggregate + residual + bias + ELU.  Warp per dst node.
// ---------------------------------------------------------------------------
__device__ __forceinline__ float lrelu(float x) { return x > 0.f ? x : 0.2f * x; }

__global__ __launch_bounds__(256) void agg_kernel(
    const float* prev_ext, const float* __restrict__ bias, int n, int use_act) {
    int w = (blockIdx.x * blockDim.x + threadIdx.x) >> 5;
    if (w >= n) return;
    const float* prev = use_act ? (const float*)g_act : prev_ext;
    int lane = threadIdx.x & 31;
    int head = lane >> 3;
    int e0 = g_off[w];
    int e1 = g_off[w + 1];

    float erh = __ldg(&g_er[w * 4 + head]);

    const uint2* hp = (const uint2*)g_hh;
    float s = 0.f;
    float4 acc = make_float4(0.f, 0.f, 0.f, 0.f);
#pragma unroll 4
    for (int i = e0; i < e1; ++i) {
        int sn = __ldg(&g_csrc[i]);
        float e = lrelu(__ldg(&g_el[sn * 4 + head]) + erh);
        float p = __expf(e);
        s += p;
        uint2 raw = __ldg(&hp[sn * 32 + lane]);
        __half2 ha = *reinterpret_cast<const __half2*>(&raw.x);
        __half2 hb = *reinterpret_cast<const __half2*>(&raw.y);
        float2 f01 = __half22float2(ha);
        float2 f23 = __half22float2(hb);
        acc.x += p * f01.x;
        acc.y += p * f01.y;
        acc.z += p * f23.x;
        acc.w += p * f23.y;
    }
    float inv = s > 0.f ? 1.f / s : 0.f;

    float4 r = ((const float4*)prev)[w * 32 + lane];
    float4 bb = ((const float4*)bias)[lane];
    float o0 = acc.x * inv + r.x + bb.x;
    float o1 = acc.y * inv + r.y + bb.y;
    float o2 = acc.z * inv + r.z + bb.z;
    float o3 = acc.w * inv + r.w + bb.w;
    o0 = o0 > 0.f ? o0 : expm1f(o0);
    o1 = o1 > 0.f ? o1 : expm1f(o1);
    o2 = o2 > 0.f ? o2 : expm1f(o2);
    o3 = o3 > 0.f ? o3 : expm1f(o3);
    ((float4*)g_act)[w * 32 + lane] = make_float4(o0, o1, o2, o3);
}

// ---------------------------------------------------------------------------
// Layer 4: warp per row.
// ---------------------------------------------------------------------------
__global__ __launch_bounds__(256) void gemv4_kernel(
    const float* __restrict__ W4, const float* __restrict__ Wres4,
    const float* __restrict__ al4, const float* __restrict__ ar4, int n) {
    int w = (blockIdx.x * blockDim.x + threadIdx.x) >> 5;
    if (w >= n) return;
    int lane = threadIdx.x & 31;
    float4 xv = ((const float4*)g_act)[w * 32 + lane];
    float4 w0 = ((const float4*)W4)[lane * 2];
    float4 w1 = ((const float4*)W4)[lane * 2 + 1];
    float4 r0 = ((const float4*)Wres4)[lane * 2];
    float4 r1 = ((const float4*)Wres4)[lane * 2 + 1];
    float h0 = xv.x * w0.x + xv.y * w0.z + xv.z * w1.x + xv.w * w1.z;
    float h1 = xv.x * w0.y + xv.y * w0.w + xv.z * w1.y + xv.w * w1.w;
    float q0 = xv.x * r0.x + xv.y * r0.z + xv.z * r1.x + xv.w * r1.z;
    float q1 = xv.x * r0.y + xv.y * r0.w + xv.z * r1.y + xv.w * r1.w;
#pragma unroll
    for (int o = 16; o; o >>= 1) {
        h0 += __shfl_xor_sync(0xffffffffu, h0, o);
        h1 += __shfl_xor_sync(0xffffffffu, h1, o);
        q0 += __shfl_xor_sync(0xffffffffu, q0, o);
        q1 += __shfl_xor_sync(0xffffffffu, q1, o);
    }
    if (lane == 0) {
        g_h4[w * 2] = h0;
        g_h4[w * 2 + 1] = h1;
        g_res4[w * 2] = q0;
        g_res4[w * 2 + 1] = q1;
        g_el4[w] = h0 * al4[0] + h1 * al4[1];
        g_er4[w] = h0 * ar4[0] + h1 * ar4[1];
    }
}

__global__ __launch_bounds__(256) void agg4_kernel(
    const float* __restrict__ b4, float* __restrict__ out, int n) {
    int w = (blockIdx.x * blockDim.x + threadIdx.x) >> 5;
    if (w >= n) return;
    int lane = threadIdx.x & 31;
    int e0 = g_off[w];
    int e1 = g_off[w + 1];
    float erv = g_er4[w];

    float s = 0.f, a0 = 0.f, a1 = 0.f;
    for (int i = e0 + lane; i < e1; i += 32) {
        int sn = g_csrc[i];
        float e = lrelu(g_el4[sn] + erv);
        float p = __expf(e);
        s += p;
        float2 hv = ((const float2*)g_h4)[sn];
        a0 += p * hv.x;
        a1 += p * hv.y;
    }
#pragma unroll
    for (int o = 16; o; o >>= 1) {
        s  += __shfl_xor_sync(0xffffffffu, s, o);
        a0 += __shfl_xor_sync(0xffffffffu, a0, o);
        a1 += __shfl_xor_sync(0xffffffffu, a1, o);
    }
    float inv = s > 0.f ? 1.f / s : 0.f;
    if (lane == 0) {
        out[w * 2]     = a0 * inv + g_res4[w * 2]     + b4[0];
        out[w * 2 + 1] = a1 * inv + g_res4[w * 2 + 1] + b4[1];
    }
}

// ---------------------------------------------------------------------------
// Constructor: EAGER loading, context, smem attribute, prewarm, aux stream.
// ---------------------------------------------------------------------------
namespace {
cudaStream_t g_saux;
cudaEvent_t  g_ev_fork;
cudaEvent_t  g_ev_join;

struct Prewarm {
    Prewarm() {
        setenv("CUDA_MODULE_LOADING", "EAGER", 1);
        cudaFree(0);

        cudaStreamCreateWithFlags(&g_saux, cudaStreamNonBlocking);
        cudaEventCreateWithFlags(&g_ev_fork, cudaEventDisableTiming);
        cudaEventCreateWithFlags(&g_ev_join, cudaEventDisableTiming);
        cudaFuncSetAttribute(gemm_tc_kernel,
                             cudaFuncAttributeMaxDynamicSharedMemorySize, SMEM_TC);

        void* ph = nullptr;
        void* pd = nullptr;
        cudaGetSymbolAddress(&ph, g_act);
        cudaGetSymbolAddress(&pd, g_deg);
        const float* fp = (const float*)ph;
        const int*   ip = (const int*)pd;
        float*       op = (float*)ph;

        int nbn = (MAXN + 255) / 256;
        int nbe = (MAXE + 255) / 256;
        int nbw = (MAXN + 7) / 8;
        int nbg = (MAXN + 127) / 128;
        int nbs = (MAXN + 1023) / 1024;
        long tot = (long)MAXN * 128;
        int nbt = (int)((tot + 255) / 256);

        touch_kernel<<<nbt, 256>>>();
        zero_kernel<<<nbn, 256>>>(0);
        hist_kernel<<<nbe, 256>>>(ip, 0);
        scan1_kernel<<<nbs, 1024>>>(0);
        scan2_kernel<<<1, 128>>>(0, 0);
        scan3_kernel<<<nbn, 256>>>(0);
        scatter_kernel<<<nbe, 256>>>(ip, ip, 0);
        gemm_tc_kernel<<<nbg, 256, SMEM_TC>>>(fp, fp, fp, fp, 0, 1);
        agg_kernel<<<nbw, 256>>>(fp, fp, 0, 1);
        gemv4_kernel<<<nbw, 256>>>(fp, fp, fp, fp, 0);
        agg4_kernel<<<nbw, 256>>>(fp, op, 0);
        zero_kernel<<<nbn, 256, 0, g_saux>>>(0);
        touch_kernel<<<nbt, 256>>>();
        cudaDeviceSynchronize();
    }
};
Prewarm g_prewarm;
}  // namespace

// ---------------------------------------------------------------------------
// Launch
// ---------------------------------------------------------------------------
extern "C" void kernel_launch(void* const* d_in, const int* in_sizes, int n_in,
                              void* d_out, int out_size) {
    const float* x     = (const float*)d_in[0];
    const int*   src   = (const int*)d_in[1];
    const int*   dst   = (const int*)d_in[2];
    const float* W1    = (const float*)d_in[3];
    const float* al1   = (const float*)d_in[4];
    const float* ar1   = (const float*)d_in[5];
    const float* b1    = (const float*)d_in[6];
    const float* W2    = (const float*)d_in[7];
    const float* al2   = (const float*)d_in[8];
    const float* ar2   = (const float*)d_in[9];
    const float* b2    = (const float*)d_in[10];
    const float* W3    = (const float*)d_in[11];
    const float* al3   = (const float*)d_in[12];
    const float* ar3   = (const float*)d_in[13];
    const float* b3    = (const float*)d_in[14];
    const float* W4    = (const float*)d_in[15];
    const float* al4   = (const float*)d_in[16];
    const float* ar4   = (const float*)d_in[17];
    const float* b4    = (const float*)d_in[18];
    const float* Wres4 = (const float*)d_in[19];
    float* out = (float*)d_out;

    int n = in_sizes[0] / 128;
    int e = in_sizes[1];
    int nb = (n + 1023) / 1024;

    int nbw = (n + 7) / 8;
    int nbg = (n + 127) / 128;

    // Fork: CSR build on aux stream, layer-1 GEMM on main stream.
    cudaEventRecord(g_ev_fork, 0);
    cudaStreamWaitEvent(g_saux, g_ev_fork, 0);

    zero_kernel<<<(n + 255) / 256, 256, 0, g_saux>>>(n);
    hist_kernel<<<(e + 255) / 256, 256, 0, g_saux>>>(dst, e);
    scan1_kernel<<<nb, 1024, 0, g_saux>>>(n);
    scan2_kernel<<<1, 128, 0, g_saux>>>(nb, n);
    scan3_kernel<<<(n + 255) / 256, 256, 0, g_saux>>>(n);
    scatter_kernel<<<(e + 255) / 256, 256, 0, g_saux>>>(src, dst, e);
    cudaEventRecord(g_ev_join, g_saux);

    gemm_tc_kernel<<<nbg, 256, SMEM_TC>>>(x, W1, al1, ar1, n, 0);

    cudaStreamWaitEvent(0, g_ev_join, 0);
    agg_kernel<<<nbw, 256>>>(x, b1, n, 0);

    gemm_tc_kernel<<<nbg, 256, SMEM_TC>>>(nullptr, W2, al2, ar2, n, 1);
    agg_kernel<<<nbw, 256>>>(nullptr, b2, n, 1);

    gemm_tc_kernel<<<nbg, 256, SMEM_TC>>>(nullptr, W3, al3, ar3, n, 1);
    agg_kernel<<<nbw, 256>>>(nullptr, b3, n, 1);

    gemv4_kernel<<<nbw, 256>>>(W4, Wres4, al4, ar4, n);
    agg4_kernel<<<nbw, 256>>>(b4, out, n);
}